// round 5
// baseline (speedup 1.0000x reference)
#include <cuda_runtime.h>
#include <cstdint>

// MultiLevelEmbedding: out[b,t,:] = emb_tables[level_ids[b,t], token_ids[b,t], :]
//                                   + level_embed[level_ids[b,t], :]
// B=64, T=1024, L=4, VOCAB=258, D=512 (float32).
//
// R5: LTS-traffic reduction. Only 1032 unique table rows; each used ~62x.
//  1) scatter_kernel: bucket positions by row id (global atomicAdd slots).
//  2) main_kernel: one block per table row; compute fused row once into
//     registers, stream 2 KB coalesced stores to every position in the
//     bucket. Block re-zeroes its counter (invariant across graph replays;
//     static zero-init covers the first call).
// LTS traffic drops 256 MB -> ~135 MB (write stream + 4 MB table reads).
// Index dtype (int64 vs int32) via per-warp ballot on odd words (<258).

#define VOCAB     258
#define L_LVL     4
#define N_ROWS    (L_LVL * VOCAB)     // 1032
#define N_POS     (64 * 1024)         // 65536 positions
#define D_VEC     128                 // float4 per row (D=512)
#define CAP       512                 // bucket capacity (mean 63.5, sigma ~8)
#define CNT_STR   40                  // counter stride in ints (160 B: spread LTS slices)

__device__ int      g_cnt[N_ROWS * CNT_STR];   // zero-init at load; re-zeroed by main
__device__ uint16_t g_bucket[N_ROWS * CAP];    // position ids per row (pos < 65536)

__global__ __launch_bounds__(256)
void scatter_kernel(const void* __restrict__ level_ids_raw,
                    const void* __restrict__ token_ids_raw,
                    const float4* __restrict__ emb_tables,
                    const float4* __restrict__ level_embed,
                    float4* __restrict__ out) {
    const int idx  = blockIdx.x * 256 + threadIdx.x;   // 0..65535
    const int lane = threadIdx.x & 31;

    // dtype detection: odd 32-bit words of first 32 token entries all zero
    // <=> int64 (values < 258; P(false positive) ~ (1/258)^32 ~ 0).
    const uint32_t* tr = (const uint32_t*)token_ids_raw;
    const unsigned nz  = __ballot_sync(0xffffffffu, tr[2 * lane + 1] != 0u);
    const bool is64    = (nz == 0u);

    int lid, tid;
    if (is64) {
        lid = (int)((const long long*)level_ids_raw)[idx];
        tid = (int)((const long long*)token_ids_raw)[idx];
    } else {
        lid = ((const int*)level_ids_raw)[idx];
        tid = ((const int*)token_ids_raw)[idx];
    }
    const int row  = lid * VOCAB + tid;
    const int slot = atomicAdd(&g_cnt[row * CNT_STR], 1);

    if (slot < CAP) {
        g_bucket[row * CAP + slot] = (uint16_t)idx;
    } else {
        // Statistically-never fallback: copy the fused row directly.
        const float4* a = emb_tables  + row * D_VEC;
        const float4* b = level_embed + lid * D_VEC;
        float4*       o = out + (long long)idx * D_VEC;
        for (int c = 0; c < D_VEC; ++c) {
            float4 va = __ldg(a + c), vb = __ldg(b + c), r;
            r.x = va.x + vb.x; r.y = va.y + vb.y;
            r.z = va.z + vb.z; r.w = va.w + vb.w;
            o[c] = r;
        }
    }
}

__global__ __launch_bounds__(128)
void main_kernel(const float4* __restrict__ emb_tables,
                 const float4* __restrict__ level_embed,
                 float4* __restrict__ out) {
    const int r   = blockIdx.x;        // table row: l*VOCAB + v
    const int tid = threadIdx.x;       // owns one float4 column

    // Fused row value, computed once, reused for every store.
    const float4 a = __ldg(emb_tables  + r * D_VEC + tid);
    const float4 b = __ldg(level_embed + (r / VOCAB) * D_VEC + tid);
    float4 v;
    v.x = a.x + b.x; v.y = a.y + b.y; v.z = a.z + b.z; v.w = a.w + b.w;

    const int n_raw = g_cnt[r * CNT_STR];
    const int n     = n_raw < CAP ? n_raw : CAP;
    const unsigned long long* bk8 =
        (const unsigned long long*)(g_bucket + r * CAP);   // 4 entries / load

    int i = 0;
    for (; i + 4 <= n; i += 4) {
        const unsigned long long w = __ldg(bk8 + (i >> 2));  // broadcast LDG.64
        const int p0 = (int)( w        & 0xFFFF);
        const int p1 = (int)((w >> 16) & 0xFFFF);
        const int p2 = (int)((w >> 32) & 0xFFFF);
        const int p3 = (int)((w >> 48) & 0xFFFF);
        out[(p0 << 7) + tid] = v;      // 4 independent coalesced STG.128
        out[(p1 << 7) + tid] = v;
        out[(p2 << 7) + tid] = v;
        out[(p3 << 7) + tid] = v;
    }
    for (; i < n; ++i) {
        const int p = g_bucket[r * CAP + i];
        out[(p << 7) + tid] = v;
    }

    // Restore counter invariant for the next replay (after all reads of n).
    __syncthreads();
    if (tid == 0) g_cnt[r * CNT_STR] = 0;
}

extern "C" void kernel_launch(void* const* d_in, const int* in_sizes, int n_in,
                              void* d_out, int out_size) {
    const void*   level_ids  = d_in[0];
    const void*   token_ids  = d_in[1];
    const float4* emb_tables = (const float4*)d_in[2];
    const float4* level_emb  = (const float4*)d_in[3];
    float4*       out        = (float4*)d_out;

    scatter_kernel<<<N_POS / 256, 256>>>(level_ids, token_ids,
                                         emb_tables, level_emb, out);
    main_kernel<<<N_ROWS, 128>>>(emb_tables, level_emb, out);
}

// round 6
// speedup vs baseline: 1.1263x; 1.1263x over previous
#include <cuda_runtime.h>
#include <cstdint>

// MultiLevelEmbedding: out[b,t,:] = emb_tables[level_ids[b,t], token_ids[b,t], :]
//                                   + level_embed[level_ids[b,t], :]
// B=64, T=1024, L=4, VOCAB=258, D=512 (float32).
//
// R6: single kernel at the DRAM-writeback wall (~24.5 us for the 134 MB
// output stream; established R3-R5: time is invariant to read traffic).
// Structure = R3's gather (2 rows/warp, 8 independent LDG.128 in flight)
// but the level_embed add is done from an 8 KB smem copy (conflict-free
// LDS.128), eliminating the fuse prologue and its launch gap entirely.
// Index dtype (int64 vs int32) via per-warp ballot on odd 32-bit words of
// token_ids (values < 258 => odd words all-zero iff int64; P(false) ~ 0).

#define D_VEC     128               // float4 per row (D=512)
#define VOCAB_SZ  258
#define L_LVL     4
#define N_POS     (64 * 1024)       // B*T rows
#define B_VEC     (L_LVL * D_VEC)   // 512 float4 = 8 KB level_embed

__global__ __launch_bounds__(256)
void mle_kernel(const void* __restrict__ level_ids_raw,
                const void* __restrict__ token_ids_raw,
                const float4* __restrict__ emb_tables,
                const float4* __restrict__ level_embed,
                float4* __restrict__ out) {
    __shared__ float4 s_b[B_VEC];   // all 4 level rows, 8 KB

    const int t    = threadIdx.x;
    const int lane = t & 31;

    // ---- preload level_embed into smem (2 float4 per thread) ----
    s_b[t]       = __ldg(level_embed + t);
    s_b[t + 256] = __ldg(level_embed + t + 256);

    // ---- dtype detection (1 LDG + ballot, warp-uniform) ----
    const uint32_t* tr = (const uint32_t*)token_ids_raw;
    const unsigned nz  = __ballot_sync(0xffffffffu, tr[2 * lane + 1] != 0u);
    const bool is64    = (nz == 0u);

    const int warp = (blockIdx.x * 256 + t) >> 5;
    const int pos0 = warp * 2;
    const int pos1 = pos0 + 1;

    // ---- warp-uniform index loads (broadcast) ----
    long long l0, t0, l1, t1;
    if (is64) {
        l0 = ((const long long*)level_ids_raw)[pos0];
        t0 = ((const long long*)token_ids_raw)[pos0];
        l1 = ((const long long*)level_ids_raw)[pos1];
        t1 = ((const long long*)token_ids_raw)[pos1];
    } else {
        l0 = ((const int*)level_ids_raw)[pos0];
        t0 = ((const int*)token_ids_raw)[pos0];
        l1 = ((const int*)level_ids_raw)[pos1];
        t1 = ((const int*)token_ids_raw)[pos1];
    }

    const float4* __restrict__ r0 = emb_tables + (l0 * VOCAB_SZ + t0) * D_VEC;
    const float4* __restrict__ r1 = emb_tables + (l1 * VOCAB_SZ + t1) * D_VEC;
    float4* __restrict__ o0 = out + (long long)pos0 * D_VEC;
    float4* __restrict__ o1 = out + (long long)pos1 * D_VEC;

    // ---- 8 independent table loads first (MLP) ----
    float4 a0 = __ldg(r0 + lane);
    float4 a1 = __ldg(r0 + lane + 32);
    float4 a2 = __ldg(r0 + lane + 64);
    float4 a3 = __ldg(r0 + lane + 96);
    float4 c0 = __ldg(r1 + lane);
    float4 c1 = __ldg(r1 + lane + 32);
    float4 c2 = __ldg(r1 + lane + 64);
    float4 c3 = __ldg(r1 + lane + 96);

    __syncthreads();                // smem table ready (overlapped with LDGs)

    const float4* __restrict__ b0r = s_b + l0 * D_VEC;
    const float4* __restrict__ b1r = s_b + l1 * D_VEC;

    float4 b, r;
    b = b0r[lane];
    r.x = a0.x + b.x; r.y = a0.y + b.y; r.z = a0.z + b.z; r.w = a0.w + b.w;
    o0[lane] = r;
    b = b0r[lane + 32];
    r.x = a1.x + b.x; r.y = a1.y + b.y; r.z = a1.z + b.z; r.w = a1.w + b.w;
    o0[lane + 32] = r;
    b = b0r[lane + 64];
    r.x = a2.x + b.x; r.y = a2.y + b.y; r.z = a2.z + b.z; r.w = a2.w + b.w;
    o0[lane + 64] = r;
    b = b0r[lane + 96];
    r.x = a3.x + b.x; r.y = a3.y + b.y; r.z = a3.z + b.z; r.w = a3.w + b.w;
    o0[lane + 96] = r;

    b = b1r[lane];
    r.x = c0.x + b.x; r.y = c0.y + b.y; r.z = c0.z + b.z; r.w = c0.w + b.w;
    o1[lane] = r;
    b = b1r[lane + 32];
    r.x = c1.x + b.x; r.y = c1.y + b.y; r.z = c1.z + b.z; r.w = c1.w + b.w;
    o1[lane + 32] = r;
    b = b1r[lane + 64];
    r.x = c2.x + b.x; r.y = c2.y + b.y; r.z = c2.z + b.z; r.w = c2.w + b.w;
    o1[lane + 64] = r;
    b = b1r[lane + 96];
    r.x = c3.x + b.x; r.y = c3.y + b.y; r.z = c3.z + b.z; r.w = c3.w + b.w;
    o1[lane + 96] = r;
}

extern "C" void kernel_launch(void* const* d_in, const int* in_sizes, int n_in,
                              void* d_out, int out_size) {
    const void*   level_ids  = d_in[0];
    const void*   token_ids  = d_in[1];
    const float4* emb_tables = (const float4*)d_in[2];
    const float4* level_emb  = (const float4*)d_in[3];
    float4*       out        = (float4*)d_out;

    // 2 rows per warp, 8 warps per block -> N_POS/16 blocks = 4096.
    mle_kernel<<<N_POS / 16, 256>>>(level_ids, token_ids,
                                    emb_tables, level_emb, out);
}

// round 7
// speedup vs baseline: 1.2029x; 1.0680x over previous
#include <cuda_runtime.h>
#include <cstdint>

// MultiLevelEmbedding: out[b,t,:] = emb_tables[level_ids[b,t], token_ids[b,t], :]
//                                   + level_embed[level_ids[b,t], :]
// B=64, T=1024, L=4, VOCAB=258, D=512 (float32).
//
// R7: R3's proven structure (fuse prologue -> pure gather at the ~24.5 us
// DRAM-writeback wall), with the prologue hidden via Programmatic Dependent
// Launch: gather blocks launch while fuse drains, do index loads + address
// math, then cudaGridDependencySynchronize() before reading g_fused.
// Index dtype (int64 vs int32) via per-warp ballot on odd 32-bit words of
// token_ids (values < 258 => odd words all-zero iff int64; P(false) ~ 0).

#define D_VEC     128                 // float4 per row (D=512)
#define VOCAB_SZ  258
#define L_LVL     4
#define N_POS     (64 * 1024)         // B*T rows
#define FUSED_N   (L_LVL * VOCAB_SZ * D_VEC)   // 132096 float4 = 2.1 MB

__device__ float4 g_fused[FUSED_N];

__global__ __launch_bounds__(256)
void fuse_kernel(const float4* __restrict__ emb_tables,
                 const float4* __restrict__ level_embed) {
    const int i   = blockIdx.x * 256 + threadIdx.x;   // covers FUSED_N exactly
    const int c   = i & (D_VEC - 1);
    const int row = i >> 7;                           // l*VOCAB + v
    const int l   = row / VOCAB_SZ;

    const float4 a = __ldg(emb_tables + i);
    const float4 b = __ldg(level_embed + l * D_VEC + c);
    float4 r;
    r.x = a.x + b.x; r.y = a.y + b.y; r.z = a.z + b.z; r.w = a.w + b.w;
    g_fused[i] = r;
}

__global__ __launch_bounds__(256)
void gather_kernel(const void* __restrict__ level_ids_raw,
                   const void* __restrict__ token_ids_raw,
                   float4* __restrict__ out) {
    const int lane = threadIdx.x & 31;
    const int warp = (blockIdx.x * 256 + threadIdx.x) >> 5;
    const int pos0 = warp * 2;                        // this warp's 2 rows
    const int pos1 = pos0 + 1;

    // ---- pre-sync work: dtype detection (1 LDG + ballot) ----
    const uint32_t* tr = (const uint32_t*)token_ids_raw;
    const unsigned nz  = __ballot_sync(0xffffffffu, tr[2 * lane + 1] != 0u);
    const bool is64    = (nz == 0u);

    // ---- pre-sync work: warp-uniform index loads (broadcast) ----
    long long l0, t0, l1, t1;
    if (is64) {
        l0 = ((const long long*)level_ids_raw)[pos0];
        t0 = ((const long long*)token_ids_raw)[pos0];
        l1 = ((const long long*)level_ids_raw)[pos1];
        t1 = ((const long long*)token_ids_raw)[pos1];
    } else {
        l0 = ((const int*)level_ids_raw)[pos0];
        t0 = ((const int*)token_ids_raw)[pos0];
        l1 = ((const int*)level_ids_raw)[pos1];
        t1 = ((const int*)token_ids_raw)[pos1];
    }

    const float4* __restrict__ r0 = g_fused + (l0 * VOCAB_SZ + t0) * D_VEC;
    const float4* __restrict__ r1 = g_fused + (l1 * VOCAB_SZ + t1) * D_VEC;
    float4* __restrict__ o0 = out + (long long)pos0 * D_VEC;
    float4* __restrict__ o1 = out + (long long)pos1 * D_VEC;

    // ---- wait for fuse_kernel's writes to be visible ----
    cudaGridDependencySynchronize();

    // ---- 8 independent loads first (MLP), then streaming stores ----
    float4 a0 = __ldg(r0 + lane);
    float4 a1 = __ldg(r0 + lane + 32);
    float4 a2 = __ldg(r0 + lane + 64);
    float4 a3 = __ldg(r0 + lane + 96);
    float4 b0 = __ldg(r1 + lane);
    float4 b1 = __ldg(r1 + lane + 32);
    float4 b2 = __ldg(r1 + lane + 64);
    float4 b3 = __ldg(r1 + lane + 96);

    __stcs(o0 + lane,      a0);
    __stcs(o0 + lane + 32, a1);
    __stcs(o0 + lane + 64, a2);
    __stcs(o0 + lane + 96, a3);
    __stcs(o1 + lane,      b0);
    __stcs(o1 + lane + 32, b1);
    __stcs(o1 + lane + 64, b2);
    __stcs(o1 + lane + 96, b3);
}

extern "C" void kernel_launch(void* const* d_in, const int* in_sizes, int n_in,
                              void* d_out, int out_size) {
    const void*   level_ids  = d_in[0];
    const void*   token_ids  = d_in[1];
    const float4* emb_tables = (const float4*)d_in[2];
    const float4* level_emb  = (const float4*)d_in[3];
    float4*       out        = (float4*)d_out;

    // Prologue: build fused table (132096/256 = 516 blocks exactly).
    fuse_kernel<<<FUSED_N / 256, 256>>>(emb_tables, level_emb);

    // Main gather, launched with programmatic stream serialization so its
    // blocks overlap the fuse kernel's tail + launch latency.
    cudaLaunchConfig_t cfg = {};
    cfg.gridDim  = dim3(N_POS / 16);   // 2 rows/warp, 8 warps/block -> 4096
    cfg.blockDim = dim3(256);
    cfg.dynamicSmemBytes = 0;
    cfg.stream = 0;                    // same (capture) stream as fuse_kernel

    cudaLaunchAttribute attrs[1];
    attrs[0].id = cudaLaunchAttributeProgrammaticStreamSerialization;
    attrs[0].val.programmaticStreamSerializationAllowed = 1;
    cfg.attrs    = attrs;
    cfg.numAttrs = 1;

    cudaLaunchKernelEx(&cfg, gather_kernel,
                       (const void*)level_ids, (const void*)token_ids, out);
}